// round 1
// baseline (speedup 1.0000x reference)
#include <cuda_runtime.h>
#include <math.h>

#define B_  2
#define T_  1024
#define D_  1024
#define H_  16
#define HD_ 64
#define FF_ 4096
#define L_  6
#define V_  50257
#define M_  (B_*T_)   // 2048 rows

// ---------------- scratch (static device globals; no allocation) -------------
__device__ float g_h   [M_*D_];
__device__ float g_ln  [M_*D_];
__device__ float g_q   [M_*D_];
__device__ float g_k   [M_*D_];
__device__ float g_v   [M_*D_];
__device__ float g_attn[M_*D_];
__device__ float g_mid [M_*FF_];

// ---------------- embedding --------------------------------------------------
__global__ void embed_kernel(const int* __restrict__ x,
                             const float* __restrict__ tok,
                             const float* __restrict__ pos,
                             float* __restrict__ h) {
    int row = blockIdx.x;            // 0..M_-1
    int t   = row % T_;
    int id  = x[row];
    const float* te = tok + (size_t)id * D_;
    const float* pe = pos + (size_t)t  * D_;
    float* o = h + (size_t)row * D_;
    for (int d = threadIdx.x; d < D_; d += blockDim.x)
        o[d] = te[d] + pe[d];
}

// ---------------- layernorm (one block per row, 256 threads) -----------------
__global__ void ln_kernel(const float* __restrict__ in,
                          const float* __restrict__ w,
                          const float* __restrict__ b,
                          float* __restrict__ out) {
    int row = blockIdx.x;
    int tid = threadIdx.x;
    const float* xr = in + (size_t)row * D_;
    float s = 0.f, sq = 0.f;
    for (int d = tid; d < D_; d += 256) {
        float v = xr[d];
        s  += v;
        sq += v * v;
    }
    __shared__ float rs[256], rq[256];
    rs[tid] = s; rq[tid] = sq;
    __syncthreads();
    for (int off = 128; off > 0; off >>= 1) {
        if (tid < off) { rs[tid] += rs[tid + off]; rq[tid] += rq[tid + off]; }
        __syncthreads();
    }
    float mu  = rs[0] * (1.f / D_);
    float var = rq[0] * (1.f / D_) - mu * mu;
    float inv = rsqrtf(var + 1e-5f);
    float* o = out + (size_t)row * D_;
    for (int d = tid; d < D_; d += 256)
        o[d] = (xr[d] - mu) * inv * w[d] + b[d];
}

// ---------------- SGEMM: C = epilogue(A[MxK] @ W[KxN] + bias) ----------------
// MODE 0: +bias     MODE 1: relu(+bias)     MODE 2: +bias + residual R
#define BM 64
#define BN 64
#define BK 16
template <int MODE>
__global__ void gemm_kernel(const float* __restrict__ A,
                            const float* __restrict__ W,
                            const float* __restrict__ bias,
                            const float* __restrict__ R,
                            float* __restrict__ C,
                            int M, int K, int N) {
    __shared__ float As[BK][BM];
    __shared__ float Ws[BK][BN];

    const int tid = threadIdx.x;        // 256
    const int bn0 = blockIdx.x * BN;
    const int bm0 = blockIdx.y * BM;
    const int tx = tid & 15;
    const int ty = tid >> 4;

    const int arow = tid >> 4;          // 0..15  (A tile: 64 rows x 16 cols)
    const int acol = tid & 15;          // 0..15
    const int wcol = tid & 63;          // 0..63  (W tile: 16 rows x 64 cols)
    const int wrow = tid >> 6;          // 0..3

    float acc[4][4];
    #pragma unroll
    for (int i = 0; i < 4; i++)
        #pragma unroll
        for (int j = 0; j < 4; j++) acc[i][j] = 0.f;

    for (int k0 = 0; k0 < K; k0 += BK) {
        #pragma unroll
        for (int i = 0; i < 4; i++) {
            int r = arow + 16 * i;
            As[acol][r] = A[(size_t)(bm0 + r) * K + (k0 + acol)];
        }
        #pragma unroll
        for (int i = 0; i < 4; i++) {
            int r = wrow + 4 * i;
            int c = bn0 + wcol;
            Ws[r][wcol] = (c < N) ? W[(size_t)(k0 + r) * N + c] : 0.f;
        }
        __syncthreads();
        #pragma unroll
        for (int kk = 0; kk < BK; kk++) {
            float4 av = *(const float4*)&As[kk][ty * 4];
            float4 bv = *(const float4*)&Ws[kk][tx * 4];
            float a[4] = {av.x, av.y, av.z, av.w};
            float b[4] = {bv.x, bv.y, bv.z, bv.w};
            #pragma unroll
            for (int i = 0; i < 4; i++)
                #pragma unroll
                for (int j = 0; j < 4; j++)
                    acc[i][j] += a[i] * b[j];
        }
        __syncthreads();
    }

    #pragma unroll
    for (int i = 0; i < 4; i++) {
        int row = bm0 + ty * 4 + i;
        #pragma unroll
        for (int j = 0; j < 4; j++) {
            int col = bn0 + tx * 4 + j;
            if (col < N) {
                float v = acc[i][j] + bias[col];
                if (MODE == 1) v = fmaxf(v, 0.f);
                if (MODE == 2) v += R[(size_t)row * N + col];
                C[(size_t)row * N + col] = v;
            }
        }
    }
}

// ---------------- causal attention: one block per (b,h,t), 128 threads -------
__global__ void attn_kernel(const float* __restrict__ q,
                            const float* __restrict__ k,
                            const float* __restrict__ v,
                            float* __restrict__ out) {
    const int idx = blockIdx.x;
    const int t = idx & (T_ - 1);
    const int h = (idx >> 10) & (H_ - 1);
    const int b = idx >> 14;
    const int tid = threadIdx.x;        // 128

    __shared__ float qs[HD_];
    __shared__ float sc[T_];
    __shared__ float tile[128][HD_ + 1];
    __shared__ float red[128];

    const size_t base = ((size_t)b * T_) * D_ + (size_t)h * HD_;

    if (tid < HD_) qs[tid] = q[base + (size_t)t * D_ + tid];
    __syncthreads();

    // pass 1: scores
    float lmax = -1e30f;
    for (int s0 = 0; s0 <= t; s0 += 128) {
        int ns = min(128, t + 1 - s0);
        for (int i = tid; i < ns * HD_; i += 128) {
            int r = i >> 6, c = i & 63;
            tile[r][c] = k[base + (size_t)(s0 + r) * D_ + c];
        }
        __syncthreads();
        if (tid < ns) {
            float d = 0.f;
            #pragma unroll
            for (int j = 0; j < HD_; j++) d += qs[j] * tile[tid][j];
            d *= 0.125f;                 // 1/sqrt(64)
            sc[s0 + tid] = d;
            lmax = fmaxf(lmax, d);
        }
        __syncthreads();
    }

    // block-reduce max
    red[tid] = lmax; __syncthreads();
    for (int off = 64; off > 0; off >>= 1) {
        if (tid < off) red[tid] = fmaxf(red[tid], red[tid + off]);
        __syncthreads();
    }
    float gmax = red[0];
    __syncthreads();

    // exp + sum
    float lsum = 0.f;
    for (int s = tid; s <= t; s += 128) {
        float e = __expf(sc[s] - gmax);
        sc[s] = e;
        lsum += e;
    }
    red[tid] = lsum; __syncthreads();
    for (int off = 64; off > 0; off >>= 1) {
        if (tid < off) red[tid] += red[tid + off];
        __syncthreads();
    }
    float inv = 1.f / red[0];
    __syncthreads();

    // pass 2: weighted sum of V
    int d0 = tid & 63, g = tid >> 6;
    float acc = 0.f;
    for (int s0 = 0; s0 <= t; s0 += 128) {
        int ns = min(128, t + 1 - s0);
        for (int i = tid; i < ns * HD_; i += 128) {
            int r = i >> 6, c = i & 63;
            tile[r][c] = v[base + (size_t)(s0 + r) * D_ + c];
        }
        __syncthreads();
        for (int r = g; r < ns; r += 2) acc += sc[s0 + r] * tile[r][d0];
        __syncthreads();
    }
    red[tid] = acc;
    __syncthreads();
    if (tid < 64)
        out[base + (size_t)t * D_ + tid] = (red[tid] + red[tid + 64]) * inv;
}

// ---------------- launch -----------------------------------------------------
extern "C" void kernel_launch(void* const* d_in, const int* in_sizes, int n_in,
                              void* d_out, int out_size) {
    const int*   x       = (const int*)  d_in[0];
    const float* tok_emb = (const float*)d_in[1];
    const float* pos_emb = (const float*)d_in[2];
    const float* wq      = (const float*)d_in[3];
    const float* bq      = (const float*)d_in[4];
    const float* wk      = (const float*)d_in[5];
    const float* bk      = (const float*)d_in[6];
    const float* wv      = (const float*)d_in[7];
    const float* bv      = (const float*)d_in[8];
    const float* wo      = (const float*)d_in[9];
    const float* bo      = (const float*)d_in[10];
    const float* ln1_w   = (const float*)d_in[11];
    const float* ln1_b   = (const float*)d_in[12];
    const float* ln2_w   = (const float*)d_in[13];
    const float* ln2_b   = (const float*)d_in[14];
    const float* ffn_w1  = (const float*)d_in[15];
    const float* ffn_b1  = (const float*)d_in[16];
    const float* ffn_w2  = (const float*)d_in[17];
    const float* ffn_b2  = (const float*)d_in[18];
    const float* lnf_w   = (const float*)d_in[19];
    const float* lnf_b   = (const float*)d_in[20];
    const float* proj_w  = (const float*)d_in[21];
    const float* proj_b  = (const float*)d_in[22];
    float* logits = (float*)d_out;

    float *h, *ln, *q, *k, *v, *attn, *mid;
    cudaGetSymbolAddress((void**)&h,    g_h);
    cudaGetSymbolAddress((void**)&ln,   g_ln);
    cudaGetSymbolAddress((void**)&q,    g_q);
    cudaGetSymbolAddress((void**)&k,    g_k);
    cudaGetSymbolAddress((void**)&v,    g_v);
    cudaGetSymbolAddress((void**)&attn, g_attn);
    cudaGetSymbolAddress((void**)&mid,  g_mid);

    embed_kernel<<<M_, 256>>>(x, tok_emb, pos_emb, h);

    dim3 gDD((D_ + BN - 1) / BN, M_ / BM);     // (16, 32)
    dim3 gDF((FF_ + BN - 1) / BN, M_ / BM);    // (64, 32)
    dim3 gDV((V_ + BN - 1) / BN, M_ / BM);     // (786, 32)

    for (int l = 0; l < L_; l++) {
        const float* wq_l = wq + (size_t)l * D_ * D_;
        const float* wk_l = wk + (size_t)l * D_ * D_;
        const float* wv_l = wv + (size_t)l * D_ * D_;
        const float* wo_l = wo + (size_t)l * D_ * D_;
        const float* w1_l = ffn_w1 + (size_t)l * D_ * FF_;
        const float* w2_l = ffn_w2 + (size_t)l * FF_ * D_;

        ln_kernel<<<M_, 256>>>(h, ln1_w + l * D_, ln1_b + l * D_, ln);

        gemm_kernel<0><<<gDD, 256>>>(ln, wq_l, bq + l * D_, nullptr, q, M_, D_, D_);
        gemm_kernel<0><<<gDD, 256>>>(ln, wk_l, bk + l * D_, nullptr, k, M_, D_, D_);
        gemm_kernel<0><<<gDD, 256>>>(ln, wv_l, bv + l * D_, nullptr, v, M_, D_, D_);

        attn_kernel<<<B_ * H_ * T_, 128>>>(q, k, v, attn);

        gemm_kernel<2><<<gDD, 256>>>(attn, wo_l, bo + l * D_, h, h, M_, D_, D_);

        ln_kernel<<<M_, 256>>>(h, ln2_w + l * D_, ln2_b + l * D_, ln);

        gemm_kernel<1><<<gDF, 256>>>(ln, w1_l, ffn_b1 + l * FF_, nullptr, mid, M_, D_, FF_);
        gemm_kernel<2><<<gDD, 256>>>(mid, w2_l, ffn_b2 + l * D_, h, h, M_, FF_, D_);
    }

    ln_kernel<<<M_, 256>>>(h, lnf_w, lnf_b, ln);
    gemm_kernel<0><<<gDV, 256>>>(ln, proj_w, proj_b, nullptr, logits, M_, D_, V_);
}

// round 2
// speedup vs baseline: 2.0677x; 2.0677x over previous
#include <cuda_runtime.h>
#include <math.h>

#define B_  2
#define T_  1024
#define D_  1024
#define H_  16
#define HD_ 64
#define FF_ 4096
#define L_  6
#define V_  50257
#define M_  (B_*T_)   // 2048 rows

// ---------------- scratch (static device globals; no allocation) -------------
__device__ float g_h   [M_*D_];
__device__ float g_ln  [M_*D_];
__device__ float g_q   [M_*D_];
__device__ float g_k   [M_*D_];
__device__ float g_v   [M_*D_];
__device__ float g_attn[M_*D_];
__device__ float g_mid [M_*FF_];

// ---------------- embedding --------------------------------------------------
__global__ void embed_kernel(const int* __restrict__ x,
                             const float* __restrict__ tok,
                             const float* __restrict__ pos,
                             float* __restrict__ h) {
    int row = blockIdx.x;
    int t   = row % T_;
    int id  = x[row];
    const float* te = tok + (size_t)id * D_;
    const float* pe = pos + (size_t)t  * D_;
    float* o = h + (size_t)row * D_;
    for (int d = threadIdx.x; d < D_; d += blockDim.x)
        o[d] = te[d] + pe[d];
}

// ---------------- layernorm (one block per row, 256 threads) -----------------
__global__ void ln_kernel(const float* __restrict__ in,
                          const float* __restrict__ w,
                          const float* __restrict__ b,
                          float* __restrict__ out) {
    int row = blockIdx.x;
    int tid = threadIdx.x;
    const float* xr = in + (size_t)row * D_;
    float s = 0.f, sq = 0.f;
    for (int d = tid; d < D_; d += 256) {
        float v = xr[d];
        s  += v;
        sq += v * v;
    }
    __shared__ float rs[256], rq[256];
    rs[tid] = s; rq[tid] = sq;
    __syncthreads();
    for (int off = 128; off > 0; off >>= 1) {
        if (tid < off) { rs[tid] += rs[tid + off]; rq[tid] += rq[tid + off]; }
        __syncthreads();
    }
    float mu  = rs[0] * (1.f / D_);
    float var = rq[0] * (1.f / D_) - mu * mu;
    float inv = rsqrtf(var + 1e-5f);
    float* o = out + (size_t)row * D_;
    for (int d = tid; d < 256 * ((D_ + 255) / 256); d += 256)
        if (d < D_) o[d] = (xr[d] - mu) * inv * w[d] + b[d];
}

// ---------------- TF32 tensor-core GEMM --------------------------------------
// C[MxN] = epilogue(A[MxK] @ W[KxN] + bias)
// MODE 0: +bias   MODE 1: relu(+bias)   MODE 2: +bias + residual R
#define BM 128
#define BN 128
#define BK 16
#define SA (BK + 4)    // As row stride: 20 floats (16B-aligned rows, conflict-free frags)
#define SB (BN + 8)    // Bs row stride: 136 floats (conflict-free frags)

__device__ __forceinline__ float f2tf(float x) {
    unsigned u;
    asm("cvt.rna.tf32.f32 %0, %1;" : "=r"(u) : "f"(x));
    return __uint_as_float(u);
}

__device__ __forceinline__ void mma8(float c[4], const unsigned a[4], const unsigned b[2]) {
    asm volatile(
        "mma.sync.aligned.m16n8k8.row.col.f32.tf32.tf32.f32 "
        "{%0,%1,%2,%3}, {%4,%5,%6,%7}, {%8,%9}, {%0,%1,%2,%3};\n"
        : "+f"(c[0]), "+f"(c[1]), "+f"(c[2]), "+f"(c[3])
        : "r"(a[0]), "r"(a[1]), "r"(a[2]), "r"(a[3]), "r"(b[0]), "r"(b[1]));
}

template <int MODE>
__device__ __forceinline__ void tgemm_body(
    const float* __restrict__ A, const float* __restrict__ W,
    const float* __restrict__ bias, const float* __restrict__ R,
    float* __restrict__ C, int K, int N, int bm0, int bn0)
{
    __shared__ float As[2][BM][SA];
    __shared__ float Bs[2][BK][SB];

    const int tid  = threadIdx.x;        // 256
    const int lane = tid & 31;
    const int warp = tid >> 5;
    const int g    = lane >> 2;          // 0..7
    const int tg   = lane & 3;           // 0..3
    const int wm0  = (warp >> 2) * 64;   // 0 / 64
    const int wn0  = (warp & 3) * 32;    // 0/32/64/96

    const bool fullB = (bn0 + BN <= N) && ((N & 3) == 0);

    float acc[4][4][4];
    #pragma unroll
    for (int mi = 0; mi < 4; mi++)
        #pragma unroll
        for (int ni = 0; ni < 4; ni++)
            #pragma unroll
            for (int r = 0; r < 4; r++) acc[mi][ni][r] = 0.f;

    float4 ra[2], rb[2];

    // ---- stage-in helpers (manually inlined twice) ----
    // A tile: 128 x 16 floats = 512 float4; thread does f = tid, tid+256
    // B tile: 16 x 128 floats = 512 float4

    // prologue: load tile k0=0
    #pragma unroll
    for (int i = 0; i < 2; i++) {
        int f = tid + i * 256;
        int row = f >> 2, c4 = (f & 3) << 2;
        ra[i] = *(const float4*)&A[(size_t)(bm0 + row) * K + c4];
    }
    #pragma unroll
    for (int i = 0; i < 2; i++) {
        int f = tid + i * 256;
        int row = f >> 5, c4 = (f & 31) << 2;
        int col = bn0 + c4;
        if (fullB) {
            rb[i] = *(const float4*)&W[(size_t)row * N + col];
        } else {
            float v[4];
            #pragma unroll
            for (int j = 0; j < 4; j++)
                v[j] = (col + j < N) ? W[(size_t)row * N + col + j] : 0.f;
            rb[i] = make_float4(v[0], v[1], v[2], v[3]);
        }
    }
    #pragma unroll
    for (int i = 0; i < 2; i++) {
        int f = tid + i * 256;
        int row = f >> 2, c4 = (f & 3) << 2;
        *(float4*)&As[0][row][c4] =
            make_float4(f2tf(ra[i].x), f2tf(ra[i].y), f2tf(ra[i].z), f2tf(ra[i].w));
    }
    #pragma unroll
    for (int i = 0; i < 2; i++) {
        int f = tid + i * 256;
        int row = f >> 5, c4 = (f & 31) << 2;
        *(float4*)&Bs[0][row][c4] =
            make_float4(f2tf(rb[i].x), f2tf(rb[i].y), f2tf(rb[i].z), f2tf(rb[i].w));
    }
    __syncthreads();

    int buf = 0;
    const int nTiles = K / BK;
    for (int t = 0; t < nTiles; t++) {
        const bool hasNext = (t + 1 < nTiles);
        const int k0n = (t + 1) * BK;
        if (hasNext) {
            #pragma unroll
            for (int i = 0; i < 2; i++) {
                int f = tid + i * 256;
                int row = f >> 2, c4 = (f & 3) << 2;
                ra[i] = *(const float4*)&A[(size_t)(bm0 + row) * K + k0n + c4];
            }
            #pragma unroll
            for (int i = 0; i < 2; i++) {
                int f = tid + i * 256;
                int row = f >> 5, c4 = (f & 31) << 2;
                int col = bn0 + c4;
                if (fullB) {
                    rb[i] = *(const float4*)&W[(size_t)(k0n + row) * N + col];
                } else {
                    float v[4];
                    #pragma unroll
                    for (int j = 0; j < 4; j++)
                        v[j] = (col + j < N) ? W[(size_t)(k0n + row) * N + col + j] : 0.f;
                    rb[i] = make_float4(v[0], v[1], v[2], v[3]);
                }
            }
        }

        // compute on buf: two k-steps of 8
        #pragma unroll
        for (int kk = 0; kk < BK; kk += 8) {
            unsigned a[4][4], b[4][2];
            #pragma unroll
            for (int mi = 0; mi < 4; mi++) {
                int r0 = wm0 + mi * 16 + g;
                a[mi][0] = __float_as_uint(As[buf][r0    ][kk + tg]);
                a[mi][1] = __float_as_uint(As[buf][r0 + 8][kk + tg]);
                a[mi][2] = __float_as_uint(As[buf][r0    ][kk + tg + 4]);
                a[mi][3] = __float_as_uint(As[buf][r0 + 8][kk + tg + 4]);
            }
            #pragma unroll
            for (int ni = 0; ni < 4; ni++) {
                int c = wn0 + ni * 8 + g;
                b[ni][0] = __float_as_uint(Bs[buf][kk + tg    ][c]);
                b[ni][1] = __float_as_uint(Bs[buf][kk + tg + 4][c]);
            }
            #pragma unroll
            for (int mi = 0; mi < 4; mi++)
                #pragma unroll
                for (int ni = 0; ni < 4; ni++)
                    mma8(acc[mi][ni], a[mi], b[ni]);
        }

        if (hasNext) {
            #pragma unroll
            for (int i = 0; i < 2; i++) {
                int f = tid + i * 256;
                int row = f >> 2, c4 = (f & 3) << 2;
                *(float4*)&As[buf ^ 1][row][c4] =
                    make_float4(f2tf(ra[i].x), f2tf(ra[i].y), f2tf(ra[i].z), f2tf(ra[i].w));
            }
            #pragma unroll
            for (int i = 0; i < 2; i++) {
                int f = tid + i * 256;
                int row = f >> 5, c4 = (f & 31) << 2;
                *(float4*)&Bs[buf ^ 1][row][c4] =
                    make_float4(f2tf(rb[i].x), f2tf(rb[i].y), f2tf(rb[i].z), f2tf(rb[i].w));
            }
        }
        __syncthreads();
        buf ^= 1;
    }

    // ---- epilogue ----
    #pragma unroll
    for (int mi = 0; mi < 4; mi++) {
        #pragma unroll
        for (int ni = 0; ni < 4; ni++) {
            int row0 = bm0 + wm0 + mi * 16 + g;
            int col0 = bn0 + wn0 + ni * 8 + 2 * tg;
            #pragma unroll
            for (int rr = 0; rr < 2; rr++) {       // row0, row0+8
                int row = row0 + rr * 8;
                #pragma unroll
                for (int cc = 0; cc < 2; cc++) {   // col0, col0+1
                    int col = col0 + cc;
                    if (col < N) {
                        float v = acc[mi][ni][rr * 2 + cc] + bias[col];
                        if (MODE == 1) v = fmaxf(v, 0.f);
                        if (MODE == 2) v += R[(size_t)row * N + col];
                        C[(size_t)row * N + col] = v;
                    }
                }
            }
        }
    }
}

template <int MODE>
__global__ __launch_bounds__(256, 2)
void tgemm(const float* __restrict__ A, const float* __restrict__ W,
           const float* __restrict__ bias, const float* __restrict__ R,
           float* __restrict__ C, int K, int N) {
    tgemm_body<MODE>(A, W, bias, R, C, K, N, blockIdx.y * BM, blockIdx.x * BN);
}

// fused QKV: gridDim.z selects which projection
__global__ __launch_bounds__(256, 2)
void tgemm_qkv(const float* __restrict__ A,
               const float* __restrict__ wq, const float* __restrict__ wk,
               const float* __restrict__ wv,
               const float* __restrict__ bq, const float* __restrict__ bk,
               const float* __restrict__ bv,
               float* __restrict__ q, float* __restrict__ k, float* __restrict__ v) {
    int z = blockIdx.z;
    const float* W    = (z == 0) ? wq : (z == 1) ? wk : wv;
    const float* bias = (z == 0) ? bq : (z == 1) ? bk : bv;
    float*       C    = (z == 0) ? q  : (z == 1) ? k  : v;
    tgemm_body<0>(A, W, bias, nullptr, C, D_, D_, blockIdx.y * BM, blockIdx.x * BN);
}

// ---------------- causal attention: one block per (b,h,t), 128 threads -------
__global__ void attn_kernel(const float* __restrict__ q,
                            const float* __restrict__ k,
                            const float* __restrict__ v,
                            float* __restrict__ out) {
    const int idx = blockIdx.x;
    const int t = idx & (T_ - 1);
    const int h = (idx >> 10) & (H_ - 1);
    const int b = idx >> 14;
    const int tid = threadIdx.x;        // 128

    __shared__ float qs[HD_];
    __shared__ float sc[T_];
    __shared__ float tile[128][HD_ + 1];
    __shared__ float red[128];

    const size_t base = ((size_t)b * T_) * D_ + (size_t)h * HD_;

    if (tid < HD_) qs[tid] = q[base + (size_t)t * D_ + tid];
    __syncthreads();

    float lmax = -1e30f;
    for (int s0 = 0; s0 <= t; s0 += 128) {
        int ns = min(128, t + 1 - s0);
        for (int i = tid; i < ns * HD_; i += 128) {
            int r = i >> 6, c = i & 63;
            tile[r][c] = k[base + (size_t)(s0 + r) * D_ + c];
        }
        __syncthreads();
        if (tid < ns) {
            float d = 0.f;
            #pragma unroll
            for (int j = 0; j < HD_; j++) d += qs[j] * tile[tid][j];
            d *= 0.125f;
            sc[s0 + tid] = d;
            lmax = fmaxf(lmax, d);
        }
        __syncthreads();
    }

    red[tid] = lmax; __syncthreads();
    for (int off = 64; off > 0; off >>= 1) {
        if (tid < off) red[tid] = fmaxf(red[tid], red[tid + off]);
        __syncthreads();
    }
    float gmax = red[0];
    __syncthreads();

    float lsum = 0.f;
    for (int s = tid; s <= t; s += 128) {
        float e = __expf(sc[s] - gmax);
        sc[s] = e;
        lsum += e;
    }
    red[tid] = lsum; __syncthreads();
    for (int off = 64; off > 0; off >>= 1) {
        if (tid < off) red[tid] += red[tid + off];
        __syncthreads();
    }
    float inv = 1.f / red[0];
    __syncthreads();

    int d0 = tid & 63, gg = tid >> 6;
    float acc = 0.f;
    for (int s0 = 0; s0 <= t; s0 += 128) {
        int ns = min(128, t + 1 - s0);
        for (int i = tid; i < ns * HD_; i += 128) {
            int r = i >> 6, c = i & 63;
            tile[r][c] = v[base + (size_t)(s0 + r) * D_ + c];
        }
        __syncthreads();
        for (int r = gg; r < ns; r += 2) acc += sc[s0 + r] * tile[r][d0];
        __syncthreads();
    }
    red[tid] = acc;
    __syncthreads();
    if (tid < 64)
        out[base + (size_t)t * D_ + tid] = (red[tid] + red[tid + 64]) * inv;
}

// ---------------- launch -----------------------------------------------------
extern "C" void kernel_launch(void* const* d_in, const int* in_sizes, int n_in,
                              void* d_out, int out_size) {
    const int*   x       = (const int*)  d_in[0];
    const float* tok_emb = (const float*)d_in[1];
    const float* pos_emb = (const float*)d_in[2];
    const float* wq      = (const float*)d_in[3];
    const float* bq      = (const float*)d_in[4];
    const float* wk      = (const float*)d_in[5];
    const float* bk      = (const float*)d_in[6];
    const float* wv      = (const float*)d_in[7];
    const float* bv      = (const float*)d_in[8];
    const float* wo      = (const float*)d_in[9];
    const float* bo      = (const float*)d_in[10];
    const float* ln1_w   = (const float*)d_in[11];
    const float* ln1_b   = (const float*)d_in[12];
    const float* ln2_w   = (const float*)d_in[13];
    const float* ln2_b   = (const float*)d_in[14];
    const float* ffn_w1  = (const float*)d_in[15];
    const float* ffn_b1  = (const float*)d_in[16];
    const float* ffn_w2  = (const float*)d_in[17];
    const float* ffn_b2  = (const float*)d_in[18];
    const float* lnf_w   = (const float*)d_in[19];
    const float* lnf_b   = (const float*)d_in[20];
    const float* proj_w  = (const float*)d_in[21];
    const float* proj_b  = (const float*)d_in[22];
    float* logits = (float*)d_out;

    float *h, *ln, *q, *k, *v, *attn, *mid;
    cudaGetSymbolAddress((void**)&h,    g_h);
    cudaGetSymbolAddress((void**)&ln,   g_ln);
    cudaGetSymbolAddress((void**)&q,    g_q);
    cudaGetSymbolAddress((void**)&k,    g_k);
    cudaGetSymbolAddress((void**)&v,    g_v);
    cudaGetSymbolAddress((void**)&attn, g_attn);
    cudaGetSymbolAddress((void**)&mid,  g_mid);

    embed_kernel<<<M_, 256>>>(x, tok_emb, pos_emb, h);

    dim3 gDD(D_ / BN, M_ / BM);              // (8, 16)
    dim3 gQKV(D_ / BN, M_ / BM, 3);          // (8, 16, 3)
    dim3 gDF(FF_ / BN, M_ / BM);             // (32, 16)
    dim3 gDV((V_ + BN - 1) / BN, M_ / BM);   // (393, 16)

    for (int l = 0; l < L_; l++) {
        const float* wq_l = wq + (size_t)l * D_ * D_;
        const float* wk_l = wk + (size_t)l * D_ * D_;
        const float* wv_l = wv + (size_t)l * D_ * D_;
        const float* wo_l = wo + (size_t)l * D_ * D_;
        const float* w1_l = ffn_w1 + (size_t)l * D_ * FF_;
        const float* w2_l = ffn_w2 + (size_t)l * FF_ * D_;

        ln_kernel<<<M_, 256>>>(h, ln1_w + l * D_, ln1_b + l * D_, ln);

        tgemm_qkv<<<gQKV, 256>>>(ln, wq_l, wk_l, wv_l,
                                 bq + l * D_, bk + l * D_, bv + l * D_, q, k, v);

        attn_kernel<<<B_ * H_ * T_, 128>>>(q, k, v, attn);

        tgemm<2><<<gDD, 256>>>(attn, wo_l, bo + l * D_, h, h, D_, D_);

        ln_kernel<<<M_, 256>>>(h, ln2_w + l * D_, ln2_b + l * D_, ln);

        tgemm<1><<<gDF, 256>>>(ln, w1_l, ffn_b1 + l * FF_, nullptr, mid, D_, FF_);
        tgemm<2><<<gDD, 256>>>(mid, w2_l, ffn_b2 + l * D_, h, h, FF_, D_);
    }

    ln_kernel<<<M_, 256>>>(h, lnf_w, lnf_b, ln);
    tgemm<0><<<gDV, 256>>>(ln, proj_w, proj_b, nullptr, logits, D_, V_);
}

// round 3
// speedup vs baseline: 2.5136x; 1.2156x over previous
#include <cuda_runtime.h>
#include <math.h>

#define B_  2
#define T_  1024
#define D_  1024
#define H_  16
#define HD_ 64
#define FF_ 4096
#define L_  6
#define V_  50257
#define M_  (B_*T_)   // 2048 rows

// ---------------- scratch (static device globals; no allocation) -------------
__device__ float g_h   [M_*D_];
__device__ float g_ln  [M_*D_];
__device__ float g_q   [M_*D_];
__device__ float g_k   [M_*D_];
__device__ float g_v   [M_*D_];
__device__ float g_attn[M_*D_];
__device__ float g_mid [M_*FF_];

// ---------------- embedding --------------------------------------------------
__global__ void embed_kernel(const int* __restrict__ x,
                             const float* __restrict__ tok,
                             const float* __restrict__ pos,
                             float* __restrict__ h) {
    int row = blockIdx.x;
    int t   = row % T_;
    int id  = x[row];
    const float* te = tok + (size_t)id * D_;
    const float* pe = pos + (size_t)t  * D_;
    float* o = h + (size_t)row * D_;
    for (int d = threadIdx.x; d < D_; d += blockDim.x)
        o[d] = te[d] + pe[d];
}

// ---------------- layernorm (one block per row, 256 threads) -----------------
__global__ void ln_kernel(const float* __restrict__ in,
                          const float* __restrict__ w,
                          const float* __restrict__ b,
                          float* __restrict__ out) {
    int row = blockIdx.x;
    int tid = threadIdx.x;
    const float* xr = in + (size_t)row * D_;
    float s = 0.f, sq = 0.f;
    for (int d = tid; d < D_; d += 256) {
        float v = xr[d];
        s  += v;
        sq += v * v;
    }
    __shared__ float rs[256], rq[256];
    rs[tid] = s; rq[tid] = sq;
    __syncthreads();
    for (int off = 128; off > 0; off >>= 1) {
        if (tid < off) { rs[tid] += rs[tid + off]; rq[tid] += rq[tid + off]; }
        __syncthreads();
    }
    float mu  = rs[0] * (1.f / D_);
    float var = rq[0] * (1.f / D_) - mu * mu;
    float inv = rsqrtf(var + 1e-5f);
    float* o = out + (size_t)row * D_;
    for (int d = tid; d < D_; d += 256)
        o[d] = (xr[d] - mu) * inv * w[d] + b[d];
}

// ---------------- TF32 tensor-core GEMM --------------------------------------
#define BM 128
#define BN 128
#define BK 16
#define SA (BK + 4)
#define SB (BN + 8)

__device__ __forceinline__ float f2tf(float x) {
    unsigned u;
    asm("cvt.rna.tf32.f32 %0, %1;" : "=r"(u) : "f"(x));
    return __uint_as_float(u);
}

__device__ __forceinline__ void mma8(float c[4], const unsigned a[4], const unsigned b[2]) {
    asm volatile(
        "mma.sync.aligned.m16n8k8.row.col.f32.tf32.tf32.f32 "
        "{%0,%1,%2,%3}, {%4,%5,%6,%7}, {%8,%9}, {%0,%1,%2,%3};\n"
        : "+f"(c[0]), "+f"(c[1]), "+f"(c[2]), "+f"(c[3])
        : "r"(a[0]), "r"(a[1]), "r"(a[2]), "r"(a[3]), "r"(b[0]), "r"(b[1]));
}

template <int MODE>
__device__ __forceinline__ void tgemm_body(
    const float* __restrict__ A, const float* __restrict__ W,
    const float* __restrict__ bias, const float* __restrict__ R,
    float* __restrict__ C, int K, int N, int bm0, int bn0)
{
    __shared__ float As[2][BM][SA];
    __shared__ float Bs[2][BK][SB];

    const int tid  = threadIdx.x;
    const int lane = tid & 31;
    const int warp = tid >> 5;
    const int g    = lane >> 2;
    const int tg   = lane & 3;
    const int wm0  = (warp >> 2) * 64;
    const int wn0  = (warp & 3) * 32;

    const bool fullB = (bn0 + BN <= N) && ((N & 3) == 0);

    float acc[4][4][4];
    #pragma unroll
    for (int mi = 0; mi < 4; mi++)
        #pragma unroll
        for (int ni = 0; ni < 4; ni++)
            #pragma unroll
            for (int r = 0; r < 4; r++) acc[mi][ni][r] = 0.f;

    float4 ra[2], rb[2];

    #pragma unroll
    for (int i = 0; i < 2; i++) {
        int f = tid + i * 256;
        int row = f >> 2, c4 = (f & 3) << 2;
        ra[i] = *(const float4*)&A[(size_t)(bm0 + row) * K + c4];
    }
    #pragma unroll
    for (int i = 0; i < 2; i++) {
        int f = tid + i * 256;
        int row = f >> 5, c4 = (f & 31) << 2;
        int col = bn0 + c4;
        if (fullB) {
            rb[i] = *(const float4*)&W[(size_t)row * N + col];
        } else {
            float v[4];
            #pragma unroll
            for (int j = 0; j < 4; j++)
                v[j] = (col + j < N) ? W[(size_t)row * N + col + j] : 0.f;
            rb[i] = make_float4(v[0], v[1], v[2], v[3]);
        }
    }
    #pragma unroll
    for (int i = 0; i < 2; i++) {
        int f = tid + i * 256;
        int row = f >> 2, c4 = (f & 3) << 2;
        *(float4*)&As[0][row][c4] =
            make_float4(f2tf(ra[i].x), f2tf(ra[i].y), f2tf(ra[i].z), f2tf(ra[i].w));
    }
    #pragma unroll
    for (int i = 0; i < 2; i++) {
        int f = tid + i * 256;
        int row = f >> 5, c4 = (f & 31) << 2;
        *(float4*)&Bs[0][row][c4] =
            make_float4(f2tf(rb[i].x), f2tf(rb[i].y), f2tf(rb[i].z), f2tf(rb[i].w));
    }
    __syncthreads();

    int buf = 0;
    const int nTiles = K / BK;
    for (int t = 0; t < nTiles; t++) {
        const bool hasNext = (t + 1 < nTiles);
        const int k0n = (t + 1) * BK;
        if (hasNext) {
            #pragma unroll
            for (int i = 0; i < 2; i++) {
                int f = tid + i * 256;
                int row = f >> 2, c4 = (f & 3) << 2;
                ra[i] = *(const float4*)&A[(size_t)(bm0 + row) * K + k0n + c4];
            }
            #pragma unroll
            for (int i = 0; i < 2; i++) {
                int f = tid + i * 256;
                int row = f >> 5, c4 = (f & 31) << 2;
                int col = bn0 + c4;
                if (fullB) {
                    rb[i] = *(const float4*)&W[(size_t)(k0n + row) * N + col];
                } else {
                    float v[4];
                    #pragma unroll
                    for (int j = 0; j < 4; j++)
                        v[j] = (col + j < N) ? W[(size_t)(k0n + row) * N + col + j] : 0.f;
                    rb[i] = make_float4(v[0], v[1], v[2], v[3]);
                }
            }
        }

        #pragma unroll
        for (int kk = 0; kk < BK; kk += 8) {
            unsigned a[4][4], b[4][2];
            #pragma unroll
            for (int mi = 0; mi < 4; mi++) {
                int r0 = wm0 + mi * 16 + g;
                a[mi][0] = __float_as_uint(As[buf][r0    ][kk + tg]);
                a[mi][1] = __float_as_uint(As[buf][r0 + 8][kk + tg]);
                a[mi][2] = __float_as_uint(As[buf][r0    ][kk + tg + 4]);
                a[mi][3] = __float_as_uint(As[buf][r0 + 8][kk + tg + 4]);
            }
            #pragma unroll
            for (int ni = 0; ni < 4; ni++) {
                int c = wn0 + ni * 8 + g;
                b[ni][0] = __float_as_uint(Bs[buf][kk + tg    ][c]);
                b[ni][1] = __float_as_uint(Bs[buf][kk + tg + 4][c]);
            }
            #pragma unroll
            for (int mi = 0; mi < 4; mi++)
                #pragma unroll
                for (int ni = 0; ni < 4; ni++)
                    mma8(acc[mi][ni], a[mi], b[ni]);
        }

        if (hasNext) {
            #pragma unroll
            for (int i = 0; i < 2; i++) {
                int f = tid + i * 256;
                int row = f >> 2, c4 = (f & 3) << 2;
                *(float4*)&As[buf ^ 1][row][c4] =
                    make_float4(f2tf(ra[i].x), f2tf(ra[i].y), f2tf(ra[i].z), f2tf(ra[i].w));
            }
            #pragma unroll
            for (int i = 0; i < 2; i++) {
                int f = tid + i * 256;
                int row = f >> 5, c4 = (f & 31) << 2;
                *(float4*)&Bs[buf ^ 1][row][c4] =
                    make_float4(f2tf(rb[i].x), f2tf(rb[i].y), f2tf(rb[i].z), f2tf(rb[i].w));
            }
        }
        __syncthreads();
        buf ^= 1;
    }

    #pragma unroll
    for (int mi = 0; mi < 4; mi++) {
        #pragma unroll
        for (int ni = 0; ni < 4; ni++) {
            int row0 = bm0 + wm0 + mi * 16 + g;
            int col0 = bn0 + wn0 + ni * 8 + 2 * tg;
            #pragma unroll
            for (int rr = 0; rr < 2; rr++) {
                int row = row0 + rr * 8;
                #pragma unroll
                for (int cc = 0; cc < 2; cc++) {
                    int col = col0 + cc;
                    if (col < N) {
                        float v = acc[mi][ni][rr * 2 + cc] + bias[col];
                        if (MODE == 1) v = fmaxf(v, 0.f);
                        if (MODE == 2) v += R[(size_t)row * N + col];
                        C[(size_t)row * N + col] = v;
                    }
                }
            }
        }
    }
}

template <int MODE>
__global__ __launch_bounds__(256, 2)
void tgemm(const float* __restrict__ A, const float* __restrict__ W,
           const float* __restrict__ bias, const float* __restrict__ R,
           float* __restrict__ C, int K, int N) {
    tgemm_body<MODE>(A, W, bias, R, C, K, N, blockIdx.y * BM, blockIdx.x * BN);
}

__global__ __launch_bounds__(256, 2)
void tgemm_qkv(const float* __restrict__ A,
               const float* __restrict__ wq, const float* __restrict__ wk,
               const float* __restrict__ wv,
               const float* __restrict__ bq, const float* __restrict__ bk,
               const float* __restrict__ bv,
               float* __restrict__ q, float* __restrict__ k, float* __restrict__ v) {
    int z = blockIdx.z;
    const float* W    = (z == 0) ? wq : (z == 1) ? wk : wv;
    const float* bias = (z == 0) ? bq : (z == 1) ? bk : bv;
    float*       C    = (z == 0) ? q  : (z == 1) ? k  : v;
    tgemm_body<0>(A, W, bias, nullptr, C, D_, D_, blockIdx.y * BM, blockIdx.x * BN);
}

// ---------------- flash attention --------------------------------------------
// grid: (T/QT, H, B), block: 256 threads. 4 threads per query row.
// Online softmax, fp32. K/V tiles of 32 rows staged through smem once per q-tile.
#define QT 64
#define KT 32

__global__ __launch_bounds__(256)
void flash_attn(const float* __restrict__ q,
                const float* __restrict__ k,
                const float* __restrict__ v,
                float* __restrict__ out) {
    const int q0  = blockIdx.x * QT;
    const int h   = blockIdx.y;
    const int b   = blockIdx.z;
    const int tid = threadIdx.x;
    const int qr  = tid >> 2;        // 0..63  query row in tile
    const int qt  = tid & 3;         // 0..3   quarter

    __shared__ float Qs[QT][68];
    __shared__ float Ks[KT][68];
    __shared__ float Vs[KT][68];
    __shared__ float Ps[QT][33];

    const size_t base = ((size_t)b * T_) * D_ + (size_t)h * HD_;
    const int qg = q0 + qr;

    // load Q tile: 64 rows x 16 float4 = 1024 float4 -> 4 per thread
    #pragma unroll
    for (int i = tid; i < QT * 16; i += 256) {
        int r = i >> 4, c4 = (i & 15) << 2;
        *(float4*)&Qs[r][c4] = *(const float4*)&q[base + (size_t)(q0 + r) * D_ + c4];
    }

    float o[16];
    #pragma unroll
    for (int i = 0; i < 16; i++) o[i] = 0.f;
    float m = -1e30f, l = 0.f;

    const int nTiles = (q0 + QT) / KT;
    __syncthreads();

    for (int t0 = 0; t0 < nTiles; t0++) {
        const int s0 = t0 * KT;
        // load K,V tiles: 32 x 16 float4 each -> 2 per thread each
        #pragma unroll
        for (int i = tid; i < KT * 16; i += 256) {
            int r = i >> 4, c4 = (i & 15) << 2;
            *(float4*)&Ks[r][c4] = *(const float4*)&k[base + (size_t)(s0 + r) * D_ + c4];
            *(float4*)&Vs[r][c4] = *(const float4*)&v[base + (size_t)(s0 + r) * D_ + c4];
        }
        __syncthreads();

        // scores for my 8 kv columns (qt*8 .. qt*8+7)
        float s[8];
        #pragma unroll
        for (int j = 0; j < 8; j++) s[j] = 0.f;
        #pragma unroll
        for (int d4 = 0; d4 < 16; d4++) {
            float4 qv = *(const float4*)&Qs[qr][d4 << 2];
            #pragma unroll
            for (int j = 0; j < 8; j++) {
                float4 kv4 = *(const float4*)&Ks[qt * 8 + j][d4 << 2];
                s[j] += qv.x * kv4.x + qv.y * kv4.y + qv.z * kv4.z + qv.w * kv4.w;
            }
        }
        // causal mask + scale
        #pragma unroll
        for (int j = 0; j < 8; j++) {
            int kvg = s0 + qt * 8 + j;
            s[j] = (kvg <= qg) ? s[j] * 0.125f : -1e30f;
        }
        // row max across 4 threads
        float tm = s[0];
        #pragma unroll
        for (int j = 1; j < 8; j++) tm = fmaxf(tm, s[j]);
        tm = fmaxf(tm, __shfl_xor_sync(0xffffffffu, tm, 1));
        tm = fmaxf(tm, __shfl_xor_sync(0xffffffffu, tm, 2));
        float m_new = fmaxf(m, tm);
        float scale = __expf(m - m_new);
        float ps = 0.f;
        #pragma unroll
        for (int j = 0; j < 8; j++) { s[j] = __expf(s[j] - m_new); ps += s[j]; }
        ps += __shfl_xor_sync(0xffffffffu, ps, 1);
        ps += __shfl_xor_sync(0xffffffffu, ps, 2);
        l = l * scale + ps;
        m = m_new;
        #pragma unroll
        for (int i = 0; i < 16; i++) o[i] *= scale;
        #pragma unroll
        for (int j = 0; j < 8; j++) Ps[qr][qt * 8 + j] = s[j];
        __syncthreads();

        // P @ V: my dims = qt*16 .. qt*16+15
        #pragma unroll 4
        for (int kv = 0; kv < KT; kv++) {
            float p = Ps[qr][kv];
            #pragma unroll
            for (int d4 = 0; d4 < 4; d4++) {
                float4 vv = *(const float4*)&Vs[kv][qt * 16 + (d4 << 2)];
                o[d4 * 4 + 0] += p * vv.x;
                o[d4 * 4 + 1] += p * vv.y;
                o[d4 * 4 + 2] += p * vv.z;
                o[d4 * 4 + 3] += p * vv.w;
            }
        }
        __syncthreads();
    }

    float inv = 1.f / l;
    #pragma unroll
    for (int d4 = 0; d4 < 4; d4++) {
        float4 ov = make_float4(o[d4 * 4 + 0] * inv, o[d4 * 4 + 1] * inv,
                                o[d4 * 4 + 2] * inv, o[d4 * 4 + 3] * inv);
        *(float4*)&out[base + (size_t)qg * D_ + qt * 16 + (d4 << 2)] = ov;
    }
}

// ---------------- launch -----------------------------------------------------
extern "C" void kernel_launch(void* const* d_in, const int* in_sizes, int n_in,
                              void* d_out, int out_size) {
    const int*   x       = (const int*)  d_in[0];
    const float* tok_emb = (const float*)d_in[1];
    const float* pos_emb = (const float*)d_in[2];
    const float* wq      = (const float*)d_in[3];
    const float* bq      = (const float*)d_in[4];
    const float* wk      = (const float*)d_in[5];
    const float* bk      = (const float*)d_in[6];
    const float* wv      = (const float*)d_in[7];
    const float* bv      = (const float*)d_in[8];
    const float* wo      = (const float*)d_in[9];
    const float* bo      = (const float*)d_in[10];
    const float* ln1_w   = (const float*)d_in[11];
    const float* ln1_b   = (const float*)d_in[12];
    const float* ln2_w   = (const float*)d_in[13];
    const float* ln2_b   = (const float*)d_in[14];
    const float* ffn_w1  = (const float*)d_in[15];
    const float* ffn_b1  = (const float*)d_in[16];
    const float* ffn_w2  = (const float*)d_in[17];
    const float* ffn_b2  = (const float*)d_in[18];
    const float* lnf_w   = (const float*)d_in[19];
    const float* lnf_b   = (const float*)d_in[20];
    const float* proj_w  = (const float*)d_in[21];
    const float* proj_b  = (const float*)d_in[22];
    float* logits = (float*)d_out;

    float *h, *ln, *q, *k, *v, *attn, *mid;
    cudaGetSymbolAddress((void**)&h,    g_h);
    cudaGetSymbolAddress((void**)&ln,   g_ln);
    cudaGetSymbolAddress((void**)&q,    g_q);
    cudaGetSymbolAddress((void**)&k,    g_k);
    cudaGetSymbolAddress((void**)&v,    g_v);
    cudaGetSymbolAddress((void**)&attn, g_attn);
    cudaGetSymbolAddress((void**)&mid,  g_mid);

    embed_kernel<<<M_, 256>>>(x, tok_emb, pos_emb, h);

    dim3 gDD(D_ / BN, M_ / BM);
    dim3 gQKV(D_ / BN, M_ / BM, 3);
    dim3 gDF(FF_ / BN, M_ / BM);
    dim3 gDV((V_ + BN - 1) / BN, M_ / BM);
    dim3 gAT(T_ / QT, H_, B_);

    for (int l = 0; l < L_; l++) {
        const float* wq_l = wq + (size_t)l * D_ * D_;
        const float* wk_l = wk + (size_t)l * D_ * D_;
        const float* wv_l = wv + (size_t)l * D_ * D_;
        const float* wo_l = wo + (size_t)l * D_ * D_;
        const float* w1_l = ffn_w1 + (size_t)l * D_ * FF_;
        const float* w2_l = ffn_w2 + (size_t)l * FF_ * D_;

        ln_kernel<<<M_, 256>>>(h, ln1_w + l * D_, ln1_b + l * D_, ln);

        tgemm_qkv<<<gQKV, 256>>>(ln, wq_l, wk_l, wv_l,
                                 bq + l * D_, bk + l * D_, bv + l * D_, q, k, v);

        flash_attn<<<gAT, 256>>>(q, k, v, attn);

        tgemm<2><<<gDD, 256>>>(attn, wo_l, bo + l * D_, h, h, D_, D_);

        ln_kernel<<<M_, 256>>>(h, ln2_w + l * D_, ln2_b + l * D_, ln);

        tgemm<1><<<gDF, 256>>>(ln, w1_l, ffn_b1 + l * FF_, nullptr, mid, D_, FF_);
        tgemm<2><<<gDD, 256>>>(mid, w2_l, ffn_b2 + l * D_, h, h, FF_, D_);
    }

    ln_kernel<<<M_, 256>>>(h, lnf_w, lnf_b, ln);
    tgemm<0><<<gDV, 256>>>(ln, proj_w, proj_b, nullptr, logits, D_, V_);
}

// round 4
// speedup vs baseline: 2.8320x; 1.1267x over previous
#include <cuda_runtime.h>
#include <math.h>

#define B_  2
#define T_  1024
#define D_  1024
#define H_  16
#define HD_ 64
#define FF_ 4096
#define L_  6
#define V_  50257
#define M_  (B_*T_)        // 2048 rows
#define VP_ 50304          // V padded to 128

// ---------------- scratch (static device globals; no allocation) -------------
__device__ float g_h   [M_*D_];
__device__ float g_ln  [M_*D_];
__device__ float g_q   [M_*D_];
__device__ float g_k   [M_*D_];
__device__ float g_v   [M_*D_];
__device__ float g_attn[M_*D_];
__device__ float g_mid [M_*FF_];
// tf32-preconverted weights
__device__ float g_cwq [L_*D_*D_];
__device__ float g_cwk [L_*D_*D_];
__device__ float g_cwv [L_*D_*D_];
__device__ float g_cwo [L_*D_*D_];
__device__ float g_cw1 [L_*D_*FF_];
__device__ float g_cw2 [L_*FF_*D_];
__device__ float g_cpj [D_*VP_];

__device__ __forceinline__ float f2tf(float x) {
    unsigned u;
    asm("cvt.rna.tf32.f32 %0, %1;" : "=r"(u) : "f"(x));
    return __uint_as_float(u);
}

// ---------------- weight conversion ------------------------------------------
__global__ void conv_tf32(const float4* __restrict__ src, float4* __restrict__ dst, int n4) {
    for (int i = blockIdx.x * blockDim.x + threadIdx.x; i < n4; i += gridDim.x * blockDim.x) {
        float4 v = src[i];
        dst[i] = make_float4(f2tf(v.x), f2tf(v.y), f2tf(v.z), f2tf(v.w));
    }
}

__global__ void conv_proj(const float* __restrict__ src, float* __restrict__ dst) {
    const long long total = (long long)D_ * VP_;
    for (long long i = (long long)blockIdx.x * blockDim.x + threadIdx.x; i < total;
         i += (long long)gridDim.x * blockDim.x) {
        int row = (int)(i / VP_), col = (int)(i - (long long)row * VP_);
        dst[i] = (col < V_) ? f2tf(src[(size_t)row * V_ + col]) : 0.f;
    }
}

// ---------------- embedding --------------------------------------------------
__global__ void embed_kernel(const int* __restrict__ x,
                             const float* __restrict__ tok,
                             const float* __restrict__ pos,
                             float* __restrict__ h) {
    int row = blockIdx.x;
    int t   = row % T_;
    int id  = x[row];
    const float* te = tok + (size_t)id * D_;
    const float* pe = pos + (size_t)t  * D_;
    float* o = h + (size_t)row * D_;
    for (int d = threadIdx.x; d < D_; d += blockDim.x)
        o[d] = te[d] + pe[d];
}

// ---------------- layernorm (tf32-rounded output) ----------------------------
__global__ void ln_kernel(const float* __restrict__ in,
                          const float* __restrict__ w,
                          const float* __restrict__ b,
                          float* __restrict__ out) {
    int row = blockIdx.x;
    int tid = threadIdx.x;
    const float* xr = in + (size_t)row * D_;
    float s = 0.f, sq = 0.f;
    for (int d = tid; d < D_; d += 256) {
        float v = xr[d];
        s  += v;
        sq += v * v;
    }
    __shared__ float rs[256], rq[256];
    rs[tid] = s; rq[tid] = sq;
    __syncthreads();
    for (int off = 128; off > 0; off >>= 1) {
        if (tid < off) { rs[tid] += rs[tid + off]; rq[tid] += rq[tid + off]; }
        __syncthreads();
    }
    float mu  = rs[0] * (1.f / D_);
    float var = rq[0] * (1.f / D_) - mu * mu;
    float inv = rsqrtf(var + 1e-5f);
    float* o = out + (size_t)row * D_;
    for (int d = tid; d < D_; d += 256)
        o[d] = f2tf((xr[d] - mu) * inv * w[d] + b[d]);
}

// ---------------- TF32 tensor-core GEMM, cp.async 3-stage --------------------
// MODE 0: +bias   MODE 1: f2tf(relu(+bias))   MODE 2: +bias + residual R
#define CPA16(dst_u32, src_ptr) \
    asm volatile("cp.async.cg.shared.global [%0], [%1], 16;" :: "r"(dst_u32), "l"(src_ptr))

__device__ __forceinline__ unsigned smem_u32(const void* p) {
    return (unsigned)__cvta_generic_to_shared(p);
}

__device__ __forceinline__ void mma8(float c[4], const unsigned a[4], const unsigned b[2]) {
    asm volatile(
        "mma.sync.aligned.m16n8k8.row.col.f32.tf32.tf32.f32 "
        "{%0,%1,%2,%3}, {%4,%5,%6,%7}, {%8,%9}, {%0,%1,%2,%3};\n"
        : "+f"(c[0]), "+f"(c[1]), "+f"(c[2]), "+f"(c[3])
        : "r"(a[0]), "r"(a[1]), "r"(a[2]), "r"(a[3]), "r"(b[0]), "r"(b[1]));
}

template <int BN_>
__device__ __forceinline__ void issue_stage(
    float* As, float* Bs, const float* A, const float* W,
    int K, int Npad, int bm0, int bn0, int k0, int tid)
{
    constexpr int SB = BN_ + 8;
    #pragma unroll
    for (int j = 0; j < 4; j++) {
        int f = tid + j * 256;
        int row = f >> 3, c4 = (f & 7) << 2;
        CPA16(smem_u32(As + row * 36 + c4), A + (size_t)(bm0 + row) * K + k0 + c4);
    }
    #pragma unroll
    for (int j = 0; j < BN_ / 32; j++) {
        int f = tid + j * 256;
        int row = (BN_ == 128) ? (f >> 5) : (f >> 4);
        int c4  = (BN_ == 128) ? ((f & 31) << 2) : ((f & 15) << 2);
        CPA16(smem_u32(Bs + row * SB + c4), W + (size_t)(k0 + row) * Npad + bn0 + c4);
    }
    asm volatile("cp.async.commit_group;");
}

template <int MODE, int BN_>
__device__ __forceinline__ void tgemm_body(
    const float* __restrict__ A, const float* __restrict__ W,
    const float* __restrict__ bias, const float* __restrict__ R,
    float* __restrict__ C, int K, int N, int Npad, int bm0, int bn0)
{
    constexpr int SB  = BN_ + 8;
    constexpr int ASZ = 128 * 36;
    constexpr int BSZ = 32 * SB;
    constexpr int NI  = BN_ / 32;       // n-tiles (of 8) per warp

    extern __shared__ float sm[];
    float* As = sm;                     // [3][128][36]
    float* Bs = sm + 3 * ASZ;           // [3][32][SB]

    const int tid  = threadIdx.x;
    const int lane = tid & 31;
    const int warp = tid >> 5;
    const int g    = lane >> 2;
    const int tg   = lane & 3;
    const int wm0  = (warp >> 2) * 64;
    const int wn0  = (warp & 3) * (BN_ / 4);

    float acc[4][NI][4];
    #pragma unroll
    for (int mi = 0; mi < 4; mi++)
        #pragma unroll
        for (int ni = 0; ni < NI; ni++)
            #pragma unroll
            for (int r = 0; r < 4; r++) acc[mi][ni][r] = 0.f;

    const int nIter = K / 32;
    issue_stage<BN_>(As, Bs, A, W, K, Npad, bm0, bn0, 0, tid);
    issue_stage<BN_>(As + ASZ, Bs + BSZ, A, W, K, Npad, bm0, bn0, 32, tid);

    int st = 0, stw = 2;
    for (int t = 0; t < nIter; t++) {
        if (t + 1 < nIter) asm volatile("cp.async.wait_group 1;");
        else               asm volatile("cp.async.wait_group 0;");
        __syncthreads();

        const float* Ast = As + st * ASZ;
        const float* Bst = Bs + st * BSZ;
        #pragma unroll
        for (int kk = 0; kk < 32; kk += 8) {
            unsigned a[4][4], b[NI][2];
            #pragma unroll
            for (int mi = 0; mi < 4; mi++) {
                int r0 = wm0 + mi * 16 + g;
                a[mi][0] = __float_as_uint(Ast[(r0    ) * 36 + kk + tg]);
                a[mi][1] = __float_as_uint(Ast[(r0 + 8) * 36 + kk + tg]);
                a[mi][2] = __float_as_uint(Ast[(r0    ) * 36 + kk + tg + 4]);
                a[mi][3] = __float_as_uint(Ast[(r0 + 8) * 36 + kk + tg + 4]);
            }
            #pragma unroll
            for (int ni = 0; ni < NI; ni++) {
                int c = wn0 + ni * 8 + g;
                b[ni][0] = __float_as_uint(Bst[(kk + tg    ) * SB + c]);
                b[ni][1] = __float_as_uint(Bst[(kk + tg + 4) * SB + c]);
            }
            #pragma unroll
            for (int mi = 0; mi < 4; mi++)
                #pragma unroll
                for (int ni = 0; ni < NI; ni++)
                    mma8(acc[mi][ni], a[mi], b[ni]);
        }

        if (t + 2 < nIter) {
            issue_stage<BN_>(As + stw * ASZ, Bs + stw * BSZ, A, W, K, Npad, bm0, bn0,
                             (t + 2) * 32, tid);
            stw = (stw == 2) ? 0 : stw + 1;
        }
        st = (st == 2) ? 0 : st + 1;
    }

    #pragma unroll
    for (int mi = 0; mi < 4; mi++) {
        #pragma unroll
        for (int ni = 0; ni < NI; ni++) {
            int row0 = bm0 + wm0 + mi * 16 + g;
            int col0 = bn0 + wn0 + ni * 8 + 2 * tg;
            #pragma unroll
            for (int rr = 0; rr < 2; rr++) {
                int row = row0 + rr * 8;
                #pragma unroll
                for (int cc = 0; cc < 2; cc++) {
                    int col = col0 + cc;
                    if (col < N) {
                        float v = acc[mi][ni][rr * 2 + cc] + bias[col];
                        if (MODE == 1) v = f2tf(fmaxf(v, 0.f));
                        if (MODE == 2) v += R[(size_t)row * N + col];
                        C[(size_t)row * N + col] = v;
                    }
                }
            }
        }
    }
}

template <int MODE, int BN_>
__global__ __launch_bounds__(256, 2)
void tgemm(const float* __restrict__ A, const float* __restrict__ W,
           const float* __restrict__ bias, const float* __restrict__ R,
           float* __restrict__ C, int K, int N, int Npad) {
    tgemm_body<MODE, BN_>(A, W, bias, R, C, K, N, Npad,
                          blockIdx.y * 128, blockIdx.x * BN_);
}

__global__ __launch_bounds__(256, 2)
void tgemm_qkv(const float* __restrict__ A,
               const float* __restrict__ wq, const float* __restrict__ wk,
               const float* __restrict__ wv,
               const float* __restrict__ bq, const float* __restrict__ bk,
               const float* __restrict__ bv,
               float* __restrict__ q, float* __restrict__ k, float* __restrict__ v) {
    int z = blockIdx.z;
    const float* W    = (z == 0) ? wq : (z == 1) ? wk : wv;
    const float* bias = (z == 0) ? bq : (z == 1) ? bk : bv;
    float*       C    = (z == 0) ? q  : (z == 1) ? k  : v;
    tgemm_body<0, 128>(A, W, bias, nullptr, C, D_, D_, D_,
                       blockIdx.y * 128, blockIdx.x * 128);
}

// ---------------- flash attention --------------------------------------------
#define QT 64
#define KT 32

__global__ __launch_bounds__(256)
void flash_attn(const float* __restrict__ q,
                const float* __restrict__ k,
                const float* __restrict__ v,
                float* __restrict__ out) {
    const int q0  = blockIdx.x * QT;
    const int h   = blockIdx.y;
    const int b   = blockIdx.z;
    const int tid = threadIdx.x;
    const int qr  = tid >> 2;
    const int qt  = tid & 3;

    __shared__ float Qs[QT][68];
    __shared__ float Ks[KT][68];
    __shared__ float Vs[KT][68];
    __shared__ float Ps[QT][33];

    const size_t base = ((size_t)b * T_) * D_ + (size_t)h * HD_;
    const int qg = q0 + qr;

    #pragma unroll
    for (int i = tid; i < QT * 16; i += 256) {
        int r = i >> 4, c4 = (i & 15) << 2;
        *(float4*)&Qs[r][c4] = *(const float4*)&q[base + (size_t)(q0 + r) * D_ + c4];
    }

    float o[16];
    #pragma unroll
    for (int i = 0; i < 16; i++) o[i] = 0.f;
    float m = -1e30f, l = 0.f;

    const int nTiles = (q0 + QT) / KT;
    __syncthreads();

    for (int t0 = 0; t0 < nTiles; t0++) {
        const int s0 = t0 * KT;
        #pragma unroll
        for (int i = tid; i < KT * 16; i += 256) {
            int r = i >> 4, c4 = (i & 15) << 2;
            *(float4*)&Ks[r][c4] = *(const float4*)&k[base + (size_t)(s0 + r) * D_ + c4];
            *(float4*)&Vs[r][c4] = *(const float4*)&v[base + (size_t)(s0 + r) * D_ + c4];
        }
        __syncthreads();

        float s[8];
        #pragma unroll
        for (int j = 0; j < 8; j++) s[j] = 0.f;
        #pragma unroll
        for (int d4 = 0; d4 < 16; d4++) {
            float4 qv = *(const float4*)&Qs[qr][d4 << 2];
            #pragma unroll
            for (int j = 0; j < 8; j++) {
                float4 kv4 = *(const float4*)&Ks[qt * 8 + j][d4 << 2];
                s[j] += qv.x * kv4.x + qv.y * kv4.y + qv.z * kv4.z + qv.w * kv4.w;
            }
        }
        #pragma unroll
        for (int j = 0; j < 8; j++) {
            int kvg = s0 + qt * 8 + j;
            s[j] = (kvg <= qg) ? s[j] * 0.125f : -1e30f;
        }
        float tm = s[0];
        #pragma unroll
        for (int j = 1; j < 8; j++) tm = fmaxf(tm, s[j]);
        tm = fmaxf(tm, __shfl_xor_sync(0xffffffffu, tm, 1));
        tm = fmaxf(tm, __shfl_xor_sync(0xffffffffu, tm, 2));
        float m_new = fmaxf(m, tm);
        float scale = __expf(m - m_new);
        float ps = 0.f;
        #pragma unroll
        for (int j = 0; j < 8; j++) { s[j] = __expf(s[j] - m_new); ps += s[j]; }
        ps += __shfl_xor_sync(0xffffffffu, ps, 1);
        ps += __shfl_xor_sync(0xffffffffu, ps, 2);
        l = l * scale + ps;
        m = m_new;
        #pragma unroll
        for (int i = 0; i < 16; i++) o[i] *= scale;
        #pragma unroll
        for (int j = 0; j < 8; j++) Ps[qr][qt * 8 + j] = s[j];
        __syncthreads();

        #pragma unroll 4
        for (int kv = 0; kv < KT; kv++) {
            float p = Ps[qr][kv];
            #pragma unroll
            for (int d4 = 0; d4 < 4; d4++) {
                float4 vv = *(const float4*)&Vs[kv][qt * 16 + (d4 << 2)];
                o[d4 * 4 + 0] += p * vv.x;
                o[d4 * 4 + 1] += p * vv.y;
                o[d4 * 4 + 2] += p * vv.z;
                o[d4 * 4 + 3] += p * vv.w;
            }
        }
        __syncthreads();
    }

    float inv = 1.f / l;
    #pragma unroll
    for (int d4 = 0; d4 < 4; d4++) {
        float4 ov = make_float4(f2tf(o[d4 * 4 + 0] * inv), f2tf(o[d4 * 4 + 1] * inv),
                                f2tf(o[d4 * 4 + 2] * inv), f2tf(o[d4 * 4 + 3] * inv));
        *(float4*)&out[base + (size_t)qg * D_ + qt * 16 + (d4 << 2)] = ov;
    }
}

// ---------------- launch -----------------------------------------------------
extern "C" void kernel_launch(void* const* d_in, const int* in_sizes, int n_in,
                              void* d_out, int out_size) {
    const int*   x       = (const int*)  d_in[0];
    const float* tok_emb = (const float*)d_in[1];
    const float* pos_emb = (const float*)d_in[2];
    const float* wq      = (const float*)d_in[3];
    const float* bq      = (const float*)d_in[4];
    const float* wk      = (const float*)d_in[5];
    const float* bk      = (const float*)d_in[6];
    const float* wv      = (const float*)d_in[7];
    const float* bv      = (const float*)d_in[8];
    const float* wo      = (const float*)d_in[9];
    const float* bo      = (const float*)d_in[10];
    const float* ln1_w   = (const float*)d_in[11];
    const float* ln1_b   = (const float*)d_in[12];
    const float* ln2_w   = (const float*)d_in[13];
    const float* ln2_b   = (const float*)d_in[14];
    const float* ffn_w1  = (const float*)d_in[15];
    const float* ffn_b1  = (const float*)d_in[16];
    const float* ffn_w2  = (const float*)d_in[17];
    const float* ffn_b2  = (const float*)d_in[18];
    const float* lnf_w   = (const float*)d_in[19];
    const float* lnf_b   = (const float*)d_in[20];
    const float* proj_w  = (const float*)d_in[21];
    const float* proj_b  = (const float*)d_in[22];
    float* logits = (float*)d_out;

    float *h, *ln, *q, *k, *v, *attn, *mid;
    float *cwq, *cwk, *cwv, *cwo, *cw1, *cw2, *cpj;
    cudaGetSymbolAddress((void**)&h,    g_h);
    cudaGetSymbolAddress((void**)&ln,   g_ln);
    cudaGetSymbolAddress((void**)&q,    g_q);
    cudaGetSymbolAddress((void**)&k,    g_k);
    cudaGetSymbolAddress((void**)&v,    g_v);
    cudaGetSymbolAddress((void**)&attn, g_attn);
    cudaGetSymbolAddress((void**)&mid,  g_mid);
    cudaGetSymbolAddress((void**)&cwq,  g_cwq);
    cudaGetSymbolAddress((void**)&cwk,  g_cwk);
    cudaGetSymbolAddress((void**)&cwv,  g_cwv);
    cudaGetSymbolAddress((void**)&cwo,  g_cwo);
    cudaGetSymbolAddress((void**)&cw1,  g_cw1);
    cudaGetSymbolAddress((void**)&cw2,  g_cw2);
    cudaGetSymbolAddress((void**)&cpj,  g_cpj);

    const int SMEM128 = 3 * (128 * 36 + 32 * 136) * 4;   // 107520 B
    const int SMEM64  = 3 * (128 * 36 + 32 * 72)  * 4;   // 82944 B
    cudaFuncSetAttribute(tgemm<0,128>, cudaFuncAttributeMaxDynamicSharedMemorySize, SMEM128);
    cudaFuncSetAttribute(tgemm<1,128>, cudaFuncAttributeMaxDynamicSharedMemorySize, SMEM128);
    cudaFuncSetAttribute(tgemm<2,64>,  cudaFuncAttributeMaxDynamicSharedMemorySize, SMEM64);
    cudaFuncSetAttribute(tgemm_qkv,    cudaFuncAttributeMaxDynamicSharedMemorySize, SMEM128);

    // ---- weight conversion (tf32 round once per call) ----
    const int sqN4 = L_ * D_ * D_ / 4;
    const int ffN4 = L_ * D_ * FF_ / 4;
    conv_tf32<<<2048, 256>>>((const float4*)wq,     (float4*)cwq, sqN4);
    conv_tf32<<<2048, 256>>>((const float4*)wk,     (float4*)cwk, sqN4);
    conv_tf32<<<2048, 256>>>((const float4*)wv,     (float4*)cwv, sqN4);
    conv_tf32<<<2048, 256>>>((const float4*)wo,     (float4*)cwo, sqN4);
    conv_tf32<<<2048, 256>>>((const float4*)ffn_w1, (float4*)cw1, ffN4);
    conv_tf32<<<2048, 256>>>((const float4*)ffn_w2, (float4*)cw2, ffN4);
    conv_proj<<<4096, 256>>>(proj_w, cpj);

    embed_kernel<<<M_, 256>>>(x, tok_emb, pos_emb, h);

    dim3 gDD64(D_ / 64, M_ / 128);          // (16,16)
    dim3 gQKV(D_ / 128, M_ / 128, 3);       // (8,16,3)
    dim3 gFF1(FF_ / 128, M_ / 128);         // (32,16)
    dim3 gPRJ(VP_ / 128, M_ / 128);         // (393,16)
    dim3 gAT(T_ / QT, H_, B_);

    for (int l = 0; l < L_; l++) {
        float* cwq_l = cwq + (size_t)l * D_ * D_;
        float* cwk_l = cwk + (size_t)l * D_ * D_;
        float* cwv_l = cwv + (size_t)l * D_ * D_;
        float* cwo_l = cwo + (size_t)l * D_ * D_;
        float* cw1_l = cw1 + (size_t)l * D_ * FF_;
        float* cw2_l = cw2 + (size_t)l * FF_ * D_;

        ln_kernel<<<M_, 256>>>(h, ln1_w + l * D_, ln1_b + l * D_, ln);

        tgemm_qkv<<<gQKV, 256, SMEM128>>>(ln, cwq_l, cwk_l, cwv_l,
                                          bq + l * D_, bk + l * D_, bv + l * D_, q, k, v);

        flash_attn<<<gAT, 256>>>(q, k, v, attn);

        tgemm<2,64><<<gDD64, 256, SMEM64>>>(attn, cwo_l, bo + l * D_, h, h, D_, D_, D_);

        ln_kernel<<<M_, 256>>>(h, ln2_w + l * D_, ln2_b + l * D_, ln);

        tgemm<1,128><<<gFF1, 256, SMEM128>>>(ln, cw1_l, ffn_b1 + l * FF_, nullptr, mid,
                                             D_, FF_, FF_);
        tgemm<2,64><<<gDD64, 256, SMEM64>>>(mid, cw2_l, ffn_b2 + l * D_, h, h, FF_, D_, D_);
    }

    ln_kernel<<<M_, 256>>>(h, lnf_w, lnf_b, ln);
    tgemm<0,128><<<gPRJ, 256, SMEM128>>>(ln, cpj, proj_b, nullptr, logits, D_, V_, VP_);
}